// round 16
// baseline (speedup 1.0000x reference)
#include <cuda_runtime.h>
#include <cuda_fp16.h>
#include <math.h>
#include <stdint.h>

// GPT-2 small forward: B=2, T=1024, E=768, H=12, hd=64, L=8, V=50257
#define BATCH 2
#define SEQ   1024
#define EMB   768
#define NH    12
#define HD    64
#define NL    8
#define VOCAB 50257
#define MROWS (BATCH*SEQ)   // 2048

// ---------------- scratch (device globals: alloc-free) ----------------
__device__ float g_x   [MROWS * EMB];
__device__ float g_h   [MROWS * EMB];
__device__ float g_qkv [MROWS * 3 * EMB];
__device__ float g_y   [MROWS * EMB];
__device__ float g_act [MROWS * 4 * EMB];

// ---------------- embedding (float4) ----------------
__global__ void embed_kernel(const int* __restrict__ idx,
                             const float* __restrict__ wte,
                             const float* __restrict__ wpe,
                             float* __restrict__ x)
{
    int i = blockIdx.x * blockDim.x + threadIdx.x;
    if (i < MROWS * EMB / 4) {
        int row = i / (EMB / 4);
        int e4  = i - row * (EMB / 4);
        int t   = row % SEQ;
        float4 a = ((const float4*)(wte + (size_t)idx[row] * EMB))[e4];
        float4 p = ((const float4*)(wpe + (size_t)t * EMB))[e4];
        a.x += p.x; a.y += p.y; a.z += p.z; a.w += p.w;
        ((float4*)x)[i] = a;
    }
}

// ---------------- layernorm: 192 threads, one float4 per thread ----------------
__global__ __launch_bounds__(192) void layernorm_kernel(
    const float* __restrict__ x, const float* __restrict__ g,
    const float* __restrict__ b, float* __restrict__ out)
{
    int row = blockIdx.x;
    int tid = threadIdx.x;
    const float4* xr = (const float4*)(x + (size_t)row * EMB);

    float4 v = xr[tid];
    float s  = v.x + v.y + v.z + v.w;
    float ss = v.x*v.x + v.y*v.y + v.z*v.z + v.w*v.w;
    #pragma unroll
    for (int o = 16; o > 0; o >>= 1) {
        s  += __shfl_xor_sync(0xffffffffu, s,  o);
        ss += __shfl_xor_sync(0xffffffffu, ss, o);
    }
    __shared__ float rs[6], rss[6];
    if ((tid & 31) == 0) { rs[tid >> 5] = s; rss[tid >> 5] = ss; }
    __syncthreads();
    float S = 0.f, SS = 0.f;
    #pragma unroll
    for (int w = 0; w < 6; w++) { S += rs[w]; SS += rss[w]; }
    float mean = S * (1.0f / EMB);
    float var  = SS * (1.0f / EMB) - mean * mean;
    float inv  = rsqrtf(var + 1e-5f);

    float4 gv = ((const float4*)g)[tid];
    float4 bv = ((const float4*)b)[tid];
    float4 o;
    o.x = (v.x - mean) * inv * gv.x + bv.x;
    o.y = (v.y - mean) * inv * gv.y + bv.y;
    o.z = (v.z - mean) * inv * gv.z + bv.z;
    o.w = (v.w - mean) * inv * gv.w + bv.w;
    ((float4*)(out + (size_t)row * EMB))[tid] = o;
}

// ---------------- helpers ----------------
__device__ __forceinline__ float gelu_tanh(float v) {
    float c = v + 0.044715f * v * v * v;
    return 0.5f * v * (1.0f + tanhf(0.7978845608028654f * c));
}

__device__ __forceinline__ uint32_t h2pack(float lo, float hi) {
    __half2 h = __floats2half2_rn(lo, hi);
    return *(uint32_t*)&h;
}

__device__ __forceinline__ void mma_f16(float* d, const uint32_t* a, const uint32_t* b) {
    asm volatile(
        "mma.sync.aligned.m16n8k16.row.col.f32.f16.f16.f32 "
        "{%0,%1,%2,%3}, {%4,%5,%6,%7}, {%8,%9}, {%0,%1,%2,%3};\n"
        : "+f"(d[0]), "+f"(d[1]), "+f"(d[2]), "+f"(d[3])
        : "r"(a[0]), "r"(a[1]), "r"(a[2]), "r"(a[3]), "r"(b[0]), "r"(b[1]));
}

// ---------------- fp16 tensor-core GEMM (m16n8k16, f32 accum) ----------------
// Template NT: warp n-tiles (8 -> BN=128, 4 -> BN=64 for small-N GEMMs).
// 8 warps (4x2), warp tile 32 x (NT*8). Double-buffered half2-packed smem.
#define TCBM 128
#define TCBK 16
#define ASTR2 20

template<int NT, bool GELU, bool RESID, bool BIAS>
__global__ __launch_bounds__(256) void gemm_tc(
    const float* __restrict__ A, const float* __restrict__ B,
    const float* __restrict__ bias, float* __restrict__ C,
    int M, int N, int K)
{
    const int BN = NT * 16;
    const int BSTR2 = BN + 8;       // %32 == 8 -> conflict-free frag loads
    __shared__ uint32_t As[2][TCBM][ASTR2];
    __shared__ uint32_t Bs[2][8][BSTR2];

    int bm = blockIdx.y * TCBM, bn = blockIdx.x * BN;
    int tid = threadIdx.x;
    int wid = tid >> 5, lane = tid & 31;
    int warpM = wid >> 1, warpN = wid & 1;

    bool nvec = ((bn + BN) <= N) && ((N & 3) == 0);

    // A loader: row arow (0..127), k-half ac (0/1) -> 8 consecutive k
    int arow = tid >> 1, ac = tid & 1;
    const float* Aptr = A + (size_t)(bm + arow) * K + ac * 8;
    // B loader: slot covers 2 k-rows x 4 cols; 2*BN slots
    bool bact = tid < 2 * BN;
    int k2r = tid / (BN / 4), nc4 = (tid % (BN / 4)) * 4;

    float acc[2][NT][4];
    #pragma unroll
    for (int mt = 0; mt < 2; mt++)
        #pragma unroll
        for (int nt = 0; nt < NT; nt++)
            #pragma unroll
            for (int c = 0; c < 4; c++) acc[mt][nt][c] = 0.f;

    float4 fa0, fa1, fb0, fb1;

    auto load_regs = [&](int k0) {
        fa0 = *(const float4*)(Aptr + k0);
        fa1 = *(const float4*)(Aptr + k0 + 4);
        if (bact) {
            const float* bp0 = B + (size_t)(k0 + 2 * k2r) * N + bn + nc4;
            const float* bp1 = bp0 + N;
            if (nvec) {
                fb0 = *(const float4*)bp0;
                fb1 = *(const float4*)bp1;
            } else {
                #pragma unroll
                for (int e = 0; e < 4; e++) {
                    int col = bn + nc4 + e;
                    ((float*)&fb0)[e] = (col < N) ? bp0[e] : 0.f;
                    ((float*)&fb1)[e] = (col < N) ? bp1[e] : 0.f;
                }
            }
        }
    };

    auto store_stage = [&](int s) {
        uint4 ua = make_uint4(h2pack(fa0.x, fa0.y), h2pack(fa0.z, fa0.w),
                              h2pack(fa1.x, fa1.y), h2pack(fa1.z, fa1.w));
        *(uint4*)&As[s][arow][ac * 4] = ua;
        if (bact) {
            uint4 ub = make_uint4(h2pack(fb0.x, fb1.x), h2pack(fb0.y, fb1.y),
                                  h2pack(fb0.z, fb1.z), h2pack(fb0.w, fb1.w));
            *(uint4*)&Bs[s][k2r][nc4] = ub;
        }
    };

    load_regs(0);
    store_stage(0);
    __syncthreads();

    const int NC = K / TCBK;
    int stage = 0;
    for (int cc = 0; cc < NC; cc++) {
        bool more = (cc + 1) < NC;
        if (more) load_regs((cc + 1) * TCBK);

        uint32_t af[2][4];
        #pragma unroll
        for (int mt = 0; mt < 2; mt++) {
            int r = warpM * 32 + mt * 16 + (lane >> 2);
            int k2 = lane & 3;
            af[mt][0] = As[stage][r    ][k2];
            af[mt][1] = As[stage][r + 8][k2];
            af[mt][2] = As[stage][r    ][k2 + 4];
            af[mt][3] = As[stage][r + 8][k2 + 4];
        }
        uint32_t bf[NT][2];
        #pragma unroll
        for (int nt = 0; nt < NT; nt++) {
            int n = warpN * (NT * 8) + nt * 8 + (lane >> 2);
            int k2 = lane & 3;
            bf[nt][0] = Bs[stage][k2    ][n];
            bf[nt][1] = Bs[stage][k2 + 4][n];
        }
        #pragma unroll
        for (int mt = 0; mt < 2; mt++)
            #pragma unroll
            for (int nt = 0; nt < NT; nt++)
                mma_f16(acc[mt][nt], af[mt], bf[nt]);

        if (more) {
            store_stage(stage ^ 1);
            __syncthreads();
            stage ^= 1;
        }
    }

    // ---- epilogue ----
    #pragma unroll
    for (int mt = 0; mt < 2; mt++) {
        int r0 = bm + warpM * 32 + mt * 16 + (lane >> 2);
        #pragma unroll
        for (int nt = 0; nt < NT; nt++) {
            int c0 = bn + warpN * (NT * 8) + nt * 8 + (lane & 3) * 2;
            float* cc2 = acc[mt][nt];
            if (nvec) {
                float2 v0 = make_float2(cc2[0], cc2[1]);
                float2 v1 = make_float2(cc2[2], cc2[3]);
                if (BIAS) {
                    float2 bb = *(const float2*)(bias + c0);
                    v0.x += bb.x; v0.y += bb.y; v1.x += bb.x; v1.y += bb.y;
                }
                if (GELU) {
                    v0.x = gelu_tanh(v0.x); v0.y = gelu_tanh(v0.y);
                    v1.x = gelu_tanh(v1.x); v1.y = gelu_tanh(v1.y);
                }
                float2* p0 = (float2*)(C + (size_t)r0 * N + c0);
                float2* p1 = (float2*)(C + (size_t)(r0 + 8) * N + c0);
                if (RESID) {
                    float2 o0 = *p0, o1 = *p1;
                    v0.x += o0.x; v0.y += o0.y; v1.x += o1.x; v1.y += o1.y;
                }
                *p0 = v0; *p1 = v1;
            } else {
                #pragma unroll
                for (int e = 0; e < 4; e++) {
                    int row = r0 + (e >> 1) * 8;
                    int col = c0 + (e & 1);
                    if (col < N) {
                        float v = cc2[e];
                        if (BIAS) v += bias[col];
                        if (GELU) v = gelu_tanh(v);
                        size_t o = (size_t)row * N + col;
                        if (RESID) v += C[o];
                        C[o] = v;
                    }
                }
            }
        }
    }
}

// ---------------- flash attention: fp32 S/softmax + fp16 mma PV ----------------
#define BQ 64
#define BKV 64
#define TSTR 68
#define PVSTR 36   // half2 words per row (32 + 4 pad); %32==4 -> conflict-free

__global__ __launch_bounds__(256) void flash_attn_kernel(
    const float* __restrict__ qkv, float* __restrict__ y)
{
    extern __shared__ float sm[];
    float*    Qs  = sm;                                // 64*68 f32
    float*    Ks  = Qs + BQ * TSTR;                    // 64*68 f32
    uint32_t* Vst = (uint32_t*)(Ks + BKV * TSTR);      // [d=64][kv2=36] half2 (V^T)
    uint32_t* Psh = Vst + HD * PVSTR;                  // [q=64][kv2=36] half2
    float*    scs = (float*)(Psh + BQ * PVSTR);        // 64 per-row rescale
    float*    ls  = scs + BQ;                          // 64 per-row l

    int qb = blockIdx.x;
    int h = blockIdx.y, b = blockIdx.z;
    int tid = threadIdx.x;
    int tx = tid & 15, ty = tid >> 4;
    int wid = tid >> 5, lane = tid & 31;
    int warpM = wid & 3, warpN = wid >> 2;   // PV frag roles: rows warpM*16.., d cols warpN*32..

    const size_t rstr = 3 * EMB;
    const float* base = qkv + (size_t)b * SEQ * rstr + h * HD;

    int lrow = tid >> 4;
    int lcol = (tid & 15) * 4;
    // V-transpose loader role: kv pair + 8-wide d block
    int kvp = tid & 31, dblk = tid >> 5;

    // ---- load Q tile (scaled) ----
    #pragma unroll
    for (int p = 0; p < 4; p++) {
        int r = p * 16 + lrow;
        float4 v = *(const float4*)(base + (size_t)(qb * BQ + r) * rstr + lcol);
        v.x *= 0.125f; v.y *= 0.125f; v.z *= 0.125f; v.w *= 0.125f;
        *(float4*)&Qs[r * TSTR + lcol] = v;
    }

    float m_i[4], l_i[4];
    #pragma unroll
    for (int i = 0; i < 4; i++) { m_i[i] = -1e30f; l_i[i] = 0.f; }
    float of[4][4];   // O fragments: warp tile 16 q-rows x 32 d
    #pragma unroll
    for (int nt = 0; nt < 4; nt++)
        #pragma unroll
        for (int c = 0; c < 4; c++) of[nt][c] = 0.f;

    int ntiles = qb + 1;
    for (int kt = 0; kt < ntiles; kt++) {
        __syncthreads();   // prior PV reads of Vst/Psh done; Q store done on iter 0

        // ---- load K (fp32) ----
        #pragma unroll
        for (int p = 0; p < 4; p++) {
            int r = p * 16 + lrow;
            *(float4*)&Ks[r * TSTR + lcol] =
                *(const float4*)(base + (size_t)(kt * BKV + r) * rstr + EMB + lcol);
        }
        // ---- load V transposed to fp16: Vst[d][kv2] ----
        {
            const float* v0p = base + (size_t)(kt * BKV + 2 * kvp) * rstr + 2 * EMB + dblk * 8;
            const float* v1p = v0p + rstr;
            float4 a0 = *(const float4*)v0p, a1 = *(const float4*)(v0p + 4);
            float4 b0 = *(const float4*)v1p, b1 = *(const float4*)(v1p + 4);
            float va[8] = {a0.x, a0.y, a0.z, a0.w, a1.x, a1.y, a1.z, a1.w};
            float vb[8] = {b0.x, b0.y, b0.z, b0.w, b1.x, b1.y, b1.z, b1.w};
            #pragma unroll
            for (int j = 0; j < 8; j++)
                Vst[(dblk * 8 + j) * PVSTR + kvp] = h2pack(va[j], vb[j]);
        }
        __syncthreads();

        // ---- S = Q @ K^T (fp32, 4x4 per thread) ----
        float S_[4][4];
        #pragma unroll
        for (int i = 0; i < 4; i++)
            #pragma unroll
            for (int j = 0; j < 4; j++) S_[i][j] = 0.f;

        #pragma unroll 4
        for (int d4 = 0; d4 < 16; d4++) {
            float4 q[4], k[4];
            #pragma unroll
            for (int i = 0; i < 4; i++)
                q[i] = *(const float4*)&Qs[(ty * 4 + i) * TSTR + d4 * 4];
            #pragma unroll
            for (int j = 0; j < 4; j++)
                k[j] = *(const float4*)&Ks[(tx * 4 + j) * TSTR + d4 * 4];
            #pragma unroll
            for (int i = 0; i < 4; i++)
                #pragma unroll
                for (int j = 0; j < 4; j++)
                    S_[i][j] += q[i].x * k[j].x + q[i].y * k[j].y
                              + q[i].z * k[j].z + q[i].w * k[j].w;
        }

        if (kt == qb) {
            #pragma unroll
            for (int i = 0; i < 4; i++) {
                int r = ty * 4 + i;
                #pragma unroll
                for (int j = 0; j < 4; j++)
                    if (tx * 4 + j > r) S_[i][j] = -1e30f;
            }
        }

        // ---- online softmax (fp32) -> Psh (fp16), scs, ls ----
        #pragma unroll
        for (int i = 0; i < 4; i++) {
            float rm = fmaxf(fmaxf(S_[i][0], S_[i][1]), fmaxf(S_[i][2], S_[i][3]));
            rm = fmaxf(rm, __shfl_xor_sync(0xffffffffu, rm, 8));
            rm = fmaxf(rm, __shfl_xor_sync(0xffffffffu, rm, 4));
            rm = fmaxf(rm, __shfl_xor_sync(0xffffffffu, rm, 2));
            rm = fmaxf(rm, __shfl_xor_sync(0xffffffffu, rm, 1));
            float mnew = fmaxf(m_i[i], rm);
            float p0 = __expf(S_[i][0] - mnew);
            float p1 = __expf(S_[i][1] - mnew);
            float p2 = __expf(S_[i][2] - mnew);
            float p3 = __expf(S_[i][3] - mnew);
            float rsum = p0 + p1 + p2 + p3;
            rsum += __shfl_xor_sync(0xffffffffu, rsum, 8);
            rsum += __shfl_xor_sync(0xffffffffu, rsum, 4);
            rsum += __shfl_xor_sync(0xffffffffu, rsum, 2);
            rsum += __shfl_xor_sync(0xffffffffu, rsum, 1);
            float sc = __expf(m_i[i] - mnew);
            l_i[i] = l_i[i] * sc + rsum;
            m_i[i] = mnew;
            int q = ty * 4 + i;
            if (tx == 0) { scs[q] = sc; ls[q] = l_i[i]; }
            uint2 pw = make_uint2(h2pack(p0, p1), h2pack(p2, p3));
            *(uint2*)&Psh[q * PVSTR + tx * 2] = pw;
        }
        __syncthreads();   // Psh/scs visible

        // ---- O = O*sc + P @ V via fp16 mma (fragment layout) ----
        {
            int rq = warpM * 16 + (lane >> 2);
            float sc0 = scs[rq], sc1 = scs[rq + 8];
            #pragma unroll
            for (int nt = 0; nt < 4; nt++) {
                of[nt][0] *= sc0; of[nt][1] *= sc0;
                of[nt][2] *= sc1; of[nt][3] *= sc1;
            }
            int r0w = rq * PVSTR, r1w = (rq + 8) * PVSTR;
            #pragma unroll
            for (int ki = 0; ki < 4; ki++) {
                int i0 = ki * 8 + (lane & 3), i1 = i0 + 4;
                uint32_t a[4];
                a[0] = Psh[r0w + i0]; a[1] = Psh[r1w + i0];
                a[2] = Psh[r0w + i1]; a[3] = Psh[r1w + i1];
                #pragma unroll
                for (int nt = 0; nt < 4; nt++) {
                    int d = warpN * 32 + nt * 8 + (lane >> 2);
                    uint32_t bb[2] = { Vst[d * PVSTR + i0], Vst[d * PVSTR + i1] };
                    mma_f16(of[nt], a, bb);
                }
            }
        }
    }

    // ---- normalize + writeout (fragment layout) ----
    {
        int rq = warpM * 16 + (lane >> 2);
        float inv0 = 1.0f / ls[rq];
        float inv1 = 1.0f / ls[rq + 8];
        int q0 = qb * BQ + rq;
        #pragma unroll
        for (int nt = 0; nt < 4; nt++) {
            int d = warpN * 32 + nt * 8 + (lane & 3) * 2;
            float2 w0 = make_float2(of[nt][0] * inv0, of[nt][1] * inv0);
            float2 w1 = make_float2(of[nt][2] * inv1, of[nt][3] * inv1);
            *(float2*)&y[((size_t)(b * SEQ + q0)) * EMB + h * HD + d] = w0;
            *(float2*)&y[((size_t)(b * SEQ + q0 + 8)) * EMB + h * HD + d] = w1;
        }
    }
}

#define FLASH_SMEM ((BQ*TSTR + BKV*TSTR) * 4 + (HD*PVSTR + BQ*PVSTR) * 4 + 2 * BQ * 4)

// ---------------- launcher ----------------
extern "C" void kernel_launch(void* const* d_in, const int* in_sizes, int n_in,
                              void* d_out, int out_size)
{
    const int*   idx    = (const int*)  d_in[0];
    const float* wte    = (const float*)d_in[1];
    const float* wpe    = (const float*)d_in[2];
    const float* ln1_g  = (const float*)d_in[3];
    const float* ln1_b  = (const float*)d_in[4];
    const float* attn_w = (const float*)d_in[5];
    const float* attn_b = (const float*)d_in[6];
    const float* proj_w = (const float*)d_in[7];
    const float* proj_b = (const float*)d_in[8];
    const float* ln2_g  = (const float*)d_in[9];
    const float* ln2_b  = (const float*)d_in[10];
    const float* mlp_w1 = (const float*)d_in[11];
    const float* mlp_b1 = (const float*)d_in[12];
    const float* mlp_w2 = (const float*)d_in[13];
    const float* mlp_b2 = (const float*)d_in[14];
    const float* lnf_g  = (const float*)d_in[15];
    const float* lnf_b  = (const float*)d_in[16];
    const float* head_w = (const float*)d_in[17];
    float* out = (float*)d_out;

    float *x, *h, *qkv, *y, *act;
    cudaGetSymbolAddress((void**)&x,   g_x);
    cudaGetSymbolAddress((void**)&h,   g_h);
    cudaGetSymbolAddress((void**)&qkv, g_qkv);
    cudaGetSymbolAddress((void**)&y,   g_y);
    cudaGetSymbolAddress((void**)&act, g_act);

    cudaFuncSetAttribute(flash_attn_kernel,
                         cudaFuncAttributeMaxDynamicSharedMemorySize, FLASH_SMEM);

    embed_kernel<<<(MROWS * EMB / 4 + 255) / 256, 256>>>(idx, wte, wpe, x);

    for (int l = 0; l < NL; l++) {
        layernorm_kernel<<<MROWS, 192>>>(x, ln1_g + l * EMB, ln1_b + l * EMB, h);

        gemm_tc<8, false, false, true><<<dim3(3 * EMB / 128, MROWS / TCBM), 256>>>(
            h, attn_w + (size_t)l * EMB * 3 * EMB, attn_b + l * 3 * EMB, qkv,
            MROWS, 3 * EMB, EMB);

        flash_attn_kernel<<<dim3(SEQ / BQ, NH, BATCH), 256, FLASH_SMEM>>>(qkv, y);

        gemm_tc<4, false, true, true><<<dim3(EMB / 64, MROWS / TCBM), 256>>>(
            y, proj_w + (size_t)l * EMB * EMB, proj_b + l * EMB, x,
            MROWS, EMB, EMB);

        layernorm_kernel<<<MROWS, 192>>>(x, ln2_g + l * EMB, ln2_b + l * EMB, h);

        gemm_tc<8, true, false, true><<<dim3(4 * EMB / 128, MROWS / TCBM), 256>>>(
            h, mlp_w1 + (size_t)l * EMB * 4 * EMB, mlp_b1 + l * 4 * EMB, act,
            MROWS, 4 * EMB, EMB);

        gemm_tc<4, false, true, true><<<dim3(EMB / 64, MROWS / TCBM), 256>>>(
            act, mlp_w2 + (size_t)l * 4 * EMB * EMB, mlp_b2 + l * EMB, x,
            MROWS, EMB, 4 * EMB);
    }

    layernorm_kernel<<<MROWS, 192>>>(x, lnf_g, lnf_b, h);

    gemm_tc<8, false, false, false><<<dim3((VOCAB + 127) / 128, MROWS / TCBM), 256>>>(
        h, head_w, nullptr, out, MROWS, VOCAB, EMB);
}

// round 17
// speedup vs baseline: 1.2920x; 1.2920x over previous
#include <cuda_runtime.h>
#include <cuda_fp16.h>
#include <math.h>
#include <stdint.h>

// GPT-2 small forward: B=2, T=1024, E=768, H=12, hd=64, L=8, V=50257
#define BATCH 2
#define SEQ   1024
#define EMB   768
#define NH    12
#define HD    64
#define NL    8
#define VOCAB 50257
#define MROWS (BATCH*SEQ)   // 2048

// ---------------- scratch (device globals: alloc-free) ----------------
__device__ float g_x   [MROWS * EMB];
__device__ float g_h   [MROWS * EMB];
__device__ float g_qkv [MROWS * 3 * EMB];
__device__ float g_y   [MROWS * EMB];
__device__ float g_act [MROWS * 4 * EMB];

// ---------------- embedding (float4) ----------------
__global__ void embed_kernel(const int* __restrict__ idx,
                             const float* __restrict__ wte,
                             const float* __restrict__ wpe,
                             float* __restrict__ x)
{
    int i = blockIdx.x * blockDim.x + threadIdx.x;
    if (i < MROWS * EMB / 4) {
        int row = i / (EMB / 4);
        int e4  = i - row * (EMB / 4);
        int t   = row % SEQ;
        float4 a = ((const float4*)(wte + (size_t)idx[row] * EMB))[e4];
        float4 p = ((const float4*)(wpe + (size_t)t * EMB))[e4];
        a.x += p.x; a.y += p.y; a.z += p.z; a.w += p.w;
        ((float4*)x)[i] = a;
    }
}

// ---------------- layernorm: 192 threads, one float4 per thread ----------------
__global__ __launch_bounds__(192) void layernorm_kernel(
    const float* __restrict__ x, const float* __restrict__ g,
    const float* __restrict__ b, float* __restrict__ out)
{
    int row = blockIdx.x;
    int tid = threadIdx.x;
    const float4* xr = (const float4*)(x + (size_t)row * EMB);

    float4 v = xr[tid];
    float s  = v.x + v.y + v.z + v.w;
    float ss = v.x*v.x + v.y*v.y + v.z*v.z + v.w*v.w;
    #pragma unroll
    for (int o = 16; o > 0; o >>= 1) {
        s  += __shfl_xor_sync(0xffffffffu, s,  o);
        ss += __shfl_xor_sync(0xffffffffu, ss, o);
    }
    __shared__ float rs[6], rss[6];
    if ((tid & 31) == 0) { rs[tid >> 5] = s; rss[tid >> 5] = ss; }
    __syncthreads();
    float S = 0.f, SS = 0.f;
    #pragma unroll
    for (int w = 0; w < 6; w++) { S += rs[w]; SS += rss[w]; }
    float mean = S * (1.0f / EMB);
    float var  = SS * (1.0f / EMB) - mean * mean;
    float inv  = rsqrtf(var + 1e-5f);

    float4 gv = ((const float4*)g)[tid];
    float4 bv = ((const float4*)b)[tid];
    float4 o;
    o.x = (v.x - mean) * inv * gv.x + bv.x;
    o.y = (v.y - mean) * inv * gv.y + bv.y;
    o.z = (v.z - mean) * inv * gv.z + bv.z;
    o.w = (v.w - mean) * inv * gv.w + bv.w;
    ((float4*)(out + (size_t)row * EMB))[tid] = o;
}

// ---------------- helpers ----------------
__device__ __forceinline__ float gelu_tanh(float v) {
    float c = v + 0.044715f * v * v * v;
    return 0.5f * v * (1.0f + tanhf(0.7978845608028654f * c));
}

__device__ __forceinline__ uint32_t h2pack(float lo, float hi) {
    __half2 h = __floats2half2_rn(lo, hi);
    return *(uint32_t*)&h;
}

__device__ __forceinline__ void mma_f16(float* d, const uint32_t* a, const uint32_t* b) {
    asm volatile(
        "mma.sync.aligned.m16n8k16.row.col.f32.f16.f16.f32 "
        "{%0,%1,%2,%3}, {%4,%5,%6,%7}, {%8,%9}, {%0,%1,%2,%3};\n"
        : "+f"(d[0]), "+f"(d[1]), "+f"(d[2]), "+f"(d[3])
        : "r"(a[0]), "r"(a[1]), "r"(a[2]), "r"(a[3]), "r"(b[0]), "r"(b[1]));
}

__device__ __forceinline__ void ldsm_x4(uint32_t& r0, uint32_t& r1,
                                        uint32_t& r2, uint32_t& r3, uint32_t addr) {
    asm volatile("ldmatrix.sync.aligned.m8n8.x4.shared.b16 {%0,%1,%2,%3}, [%4];"
                 : "=r"(r0), "=r"(r1), "=r"(r2), "=r"(r3) : "r"(addr));
}

// ---------------- fp16 tensor-core GEMM (m16n8k16, f32 accum) ----------------
// 128x128 tile, BK=16, 256 thr, 8 warps (4x2), warp tile 32x64.
// Double-buffered half2-packed smem:
//  A: As[m][k2] words (8 used of 20 stride); A-frags via ldmatrix.x4
//     (lane-phase banks 20r mod 32 distinct -> conflict-free)
//  B: Bs[k2][n] words, stride 136 (%32==8 -> conflict-free scalar frag loads)
#define TCBM 128
#define TCBK 16
#define ASTR2 20
#define BSTR2 136

template<bool GELU, bool RESID, bool BIAS>
__global__ __launch_bounds__(256) void gemm_tc(
    const float* __restrict__ A, const float* __restrict__ B,
    const float* __restrict__ bias, float* __restrict__ C,
    int M, int N, int K)
{
    __shared__ uint32_t As[2][TCBM][ASTR2];   // 20,480 B
    __shared__ uint32_t Bs[2][8][BSTR2];      //  8,704 B

    int bm = blockIdx.y * TCBM, bn = blockIdx.x * 128;
    int tid = threadIdx.x;
    int wid = tid >> 5, lane = tid & 31;
    int warpM = wid >> 1, warpN = wid & 1;

    bool nvec = ((bn + 128) <= N) && ((N & 3) == 0);

    // A loader: row arow (0..127), k-half ac (0/1) -> 8 consecutive k
    int arow = tid >> 1, ac = tid & 1;
    const float* Aptr = A + (size_t)(bm + arow) * K + ac * 8;
    // B loader: k2 row k2r (0..7) covers rows 2*k2r, 2*k2r+1; cols nc4..nc4+3
    int k2r = tid >> 5, nc4 = (tid & 31) * 4;

    // ldmatrix lane address components (row within warp A tile, 16B col half)
    int lm_row = lane & 15;
    int lm_col = (lane >> 4) * 4;

    float acc[2][8][4];
    #pragma unroll
    for (int mt = 0; mt < 2; mt++)
        #pragma unroll
        for (int nt = 0; nt < 8; nt++)
            #pragma unroll
            for (int c = 0; c < 4; c++) acc[mt][nt][c] = 0.f;

    float4 fa0, fa1, fb0, fb1;

    auto load_regs = [&](int k0) {
        fa0 = *(const float4*)(Aptr + k0);
        fa1 = *(const float4*)(Aptr + k0 + 4);
        const float* bp0 = B + (size_t)(k0 + 2 * k2r) * N + bn + nc4;
        const float* bp1 = bp0 + N;
        if (nvec) {
            fb0 = *(const float4*)bp0;
            fb1 = *(const float4*)bp1;
        } else {
            #pragma unroll
            for (int e = 0; e < 4; e++) {
                int col = bn + nc4 + e;
                ((float*)&fb0)[e] = (col < N) ? bp0[e] : 0.f;
                ((float*)&fb1)[e] = (col < N) ? bp1[e] : 0.f;
            }
        }
    };

    auto store_stage = [&](int s) {
        uint4 ua = make_uint4(h2pack(fa0.x, fa0.y), h2pack(fa0.z, fa0.w),
                              h2pack(fa1.x, fa1.y), h2pack(fa1.z, fa1.w));
        *(uint4*)&As[s][arow][ac * 4] = ua;
        uint4 ub = make_uint4(h2pack(fb0.x, fb1.x), h2pack(fb0.y, fb1.y),
                              h2pack(fb0.z, fb1.z), h2pack(fb0.w, fb1.w));
        *(uint4*)&Bs[s][k2r][nc4] = ub;
    };

    load_regs(0);
    store_stage(0);
    __syncthreads();

    const int NC = K / TCBK;
    int stage = 0;
    for (int cc = 0; cc < NC; cc++) {
        bool more = (cc + 1) < NC;
        if (more) load_regs((cc + 1) * TCBK);

        // ---- A fragments via ldmatrix.x4 (2 instr instead of 8 LDS.32) ----
        uint32_t af[2][4];
        #pragma unroll
        for (int mt = 0; mt < 2; mt++) {
            int r = warpM * 32 + mt * 16 + lm_row;
            uint32_t addr = (uint32_t)__cvta_generic_to_shared(&As[stage][r][lm_col]);
            ldsm_x4(af[mt][0], af[mt][1], af[mt][2], af[mt][3], addr);
        }
        uint32_t bf[8][2];
        #pragma unroll
        for (int nt = 0; nt < 8; nt++) {
            int n = warpN * 64 + nt * 8 + (lane >> 2);
            int k2 = lane & 3;
            bf[nt][0] = Bs[stage][k2    ][n];
            bf[nt][1] = Bs[stage][k2 + 4][n];
        }
        #pragma unroll
        for (int mt = 0; mt < 2; mt++)
            #pragma unroll
            for (int nt = 0; nt < 8; nt++)
                mma_f16(acc[mt][nt], af[mt], bf[nt]);

        if (more) {
            store_stage(stage ^ 1);
            __syncthreads();
            stage ^= 1;
        }
    }

    // ---- epilogue ----
    #pragma unroll
    for (int mt = 0; mt < 2; mt++) {
        int r0 = bm + warpM * 32 + mt * 16 + (lane >> 2);
        #pragma unroll
        for (int nt = 0; nt < 8; nt++) {
            int c0 = bn + warpN * 64 + nt * 8 + (lane & 3) * 2;
            float* cc2 = acc[mt][nt];
            if (nvec) {
                float2 v0 = make_float2(cc2[0], cc2[1]);
                float2 v1 = make_float2(cc2[2], cc2[3]);
                if (BIAS) {
                    float2 bb = *(const float2*)(bias + c0);
                    v0.x += bb.x; v0.y += bb.y; v1.x += bb.x; v1.y += bb.y;
                }
                if (GELU) {
                    v0.x = gelu_tanh(v0.x); v0.y = gelu_tanh(v0.y);
                    v1.x = gelu_tanh(v1.x); v1.y = gelu_tanh(v1.y);
                }
                float2* p0 = (float2*)(C + (size_t)r0 * N + c0);
                float2* p1 = (float2*)(C + (size_t)(r0 + 8) * N + c0);
                if (RESID) {
                    float2 o0 = *p0, o1 = *p1;
                    v0.x += o0.x; v0.y += o0.y; v1.x += o1.x; v1.y += o1.y;
                }
                *p0 = v0; *p1 = v1;
            } else {
                #pragma unroll
                for (int e = 0; e < 4; e++) {
                    int row = r0 + (e >> 1) * 8;
                    int col = c0 + (e & 1);
                    if (col < N) {
                        float v = cc2[e];
                        if (BIAS) v += bias[col];
                        if (GELU) v = gelu_tanh(v);
                        size_t o = (size_t)row * N + col;
                        if (RESID) v += C[o];
                        C[o] = v;
                    }
                }
            }
        }
    }
}

// ---------------- flash attention (R13: fp32 throughout) ----------------
#define BQ 64
#define BKV 64
#define TSTR 68

__global__ __launch_bounds__(256) void flash_attn_kernel(
    const float* __restrict__ qkv, float* __restrict__ y)
{
    extern __shared__ float sm[];
    float* Qs = sm;
    float* Ks = Qs + BQ * TSTR;
    float* Vs = Ks + BKV * TSTR;
    float* Ps = Vs + BKV * TSTR;

    int qb = blockIdx.x;
    int h = blockIdx.y, b = blockIdx.z;
    int tid = threadIdx.x;
    int tx = tid & 15, ty = tid >> 4;

    const size_t rstr = 3 * EMB;
    const float* base = qkv + (size_t)b * SEQ * rstr + h * HD;

    int lrow = tid >> 4;
    int lcol = (tid & 15) * 4;

    #pragma unroll
    for (int p = 0; p < 4; p++) {
        int r = p * 16 + lrow;
        float4 v = *(const float4*)(base + (size_t)(qb * BQ + r) * rstr + lcol);
        v.x *= 0.125f; v.y *= 0.125f; v.z *= 0.125f; v.w *= 0.125f;
        *(float4*)&Qs[r * TSTR + lcol] = v;
    }

    float O[4][4];
    float m_i[4], l_i[4];
    #pragma unroll
    for (int i = 0; i < 4; i++) {
        m_i[i] = -1e30f; l_i[i] = 0.f;
        #pragma unroll
        for (int j = 0; j < 4; j++) O[i][j] = 0.f;
    }

    int ntiles = qb + 1;
    for (int kt = 0; kt < ntiles; kt++) {
        __syncthreads();

        #pragma unroll
        for (int p = 0; p < 4; p++) {
            int r = p * 16 + lrow;
            size_t grow = (size_t)(kt * BKV + r) * rstr;
            *(float4*)&Ks[r * TSTR + lcol] = *(const float4*)(base + grow + EMB + lcol);
            *(float4*)&Vs[r * TSTR + lcol] = *(const float4*)(base + grow + 2 * EMB + lcol);
        }
        __syncthreads();

        float S_[4][4];
        #pragma unroll
        for (int i = 0; i < 4; i++)
            #pragma unroll
            for (int j = 0; j < 4; j++) S_[i][j] = 0.f;

        #pragma unroll 4
        for (int d4 = 0; d4 < 16; d4++) {
            float4 q[4], k[4];
            #pragma unroll
            for (int i = 0; i < 4; i++)
                q[i] = *(const float4*)&Qs[(ty * 4 + i) * TSTR + d4 * 4];
            #pragma unroll
            for (int j = 0; j < 4; j++)
                k[j] = *(const float4*)&Ks[(tx * 4 + j) * TSTR + d4 * 4];
            #pragma unroll
            for (int i = 0; i < 4; i++)
                #pragma unroll
                for (int j = 0; j < 4; j++)
                    S_[i][j] += q[i].x * k[j].x + q[i].y * k[j].y
                              + q[i].z * k[j].z + q[i].w * k[j].w;
        }

        if (kt == qb) {
            #pragma unroll
            for (int i = 0; i < 4; i++) {
                int r = ty * 4 + i;
                #pragma unroll
                for (int j = 0; j < 4; j++)
                    if (tx * 4 + j > r) S_[i][j] = -1e30f;
            }
        }

        #pragma unroll
        for (int i = 0; i < 4; i++) {
            float rm = fmaxf(fmaxf(S_[i][0], S_[i][1]), fmaxf(S_[i][2], S_[i][3]));
            rm = fmaxf(rm, __shfl_xor_sync(0xffffffffu, rm, 8));
            rm = fmaxf(rm, __shfl_xor_sync(0xffffffffu, rm, 4));
            rm = fmaxf(rm, __shfl_xor_sync(0xffffffffu, rm, 2));
            rm = fmaxf(rm, __shfl_xor_sync(0xffffffffu, rm, 1));
            float mnew = fmaxf(m_i[i], rm);
            float p0 = __expf(S_[i][0] - mnew);
            float p1 = __expf(S_[i][1] - mnew);
            float p2 = __expf(S_[i][2] - mnew);
            float p3 = __expf(S_[i][3] - mnew);
            float rsum = p0 + p1 + p2 + p3;
            rsum += __shfl_xor_sync(0xffffffffu, rsum, 8);
            rsum += __shfl_xor_sync(0xffffffffu, rsum, 4);
            rsum += __shfl_xor_sync(0xffffffffu, rsum, 2);
            rsum += __shfl_xor_sync(0xffffffffu, rsum, 1);
            float sc = __expf(m_i[i] - mnew);
            l_i[i] = l_i[i] * sc + rsum;
            m_i[i] = mnew;
            O[i][0] *= sc; O[i][1] *= sc; O[i][2] *= sc; O[i][3] *= sc;
            *(float4*)&Ps[(ty * 4 + i) * TSTR + tx * 4] = make_float4(p0, p1, p2, p3);
        }
        __syncthreads();

        #pragma unroll 8
        for (int k = 0; k < BKV; k++) {
            float4 v = *(const float4*)&Vs[k * TSTR + tx * 4];
            #pragma unroll
            for (int i = 0; i < 4; i++) {
                float p = Ps[(ty * 4 + i) * TSTR + k];
                O[i][0] += p * v.x; O[i][1] += p * v.y;
                O[i][2] += p * v.z; O[i][3] += p * v.w;
            }
        }
    }

    #pragma unroll
    for (int i = 0; i < 4; i++) {
        float inv = 1.0f / l_i[i];
        int q = qb * BQ + ty * 4 + i;
        float4 o = make_float4(O[i][0] * inv, O[i][1] * inv,
                               O[i][2] * inv, O[i][3] * inv);
        *(float4*)&y[((size_t)(b * SEQ + q)) * EMB + h * HD + tx * 4] = o;
    }
}

#define FLASH_SMEM ((2*BQ + 2*BKV) * TSTR * 4)

// ---------------- launcher ----------------
extern "C" void kernel_launch(void* const* d_in, const int* in_sizes, int n_in,
                              void* d_out, int out_size)
{
    const int*   idx    = (const int*)  d_in[0];
    const float* wte    = (const float*)d_in[1];
    const float* wpe    = (const float*)d_in[2];
    const float* ln1_g  = (const float*)d_in[3];
    const float* ln1_b  = (const float*)d_in[4];
    const float* attn_w = (const float*)d_in[5];
    const float* attn_b = (const float*)d_in[6];
    const float* proj_w = (const float*)d_in[7];
    const float* proj_b = (const float*)d_in[8];
    const float* ln2_g  = (const float*)d_in[9];
    const float* ln2_b  = (const float*)d_in[10];
    const float* mlp_w1 = (const float*)d_in[11];
    const float* mlp_b1 = (const float*)d_in[12];
    const float* mlp_w2 = (const float*)d_in[13];
    const float* mlp_b2 = (const float*)d_in[14];
    const float* lnf_g  = (const float*)d_in[15];
    const float* lnf_b  = (const float*)d_in[16];
    const float* head_w = (const float*)d_in[17];
    float* out = (float*)d_out;

    float *x, *h, *qkv, *y, *act;
    cudaGetSymbolAddress((void**)&x,   g_x);
    cudaGetSymbolAddress((void**)&h,   g_h);
    cudaGetSymbolAddress((void**)&qkv, g_qkv);
    cudaGetSymbolAddress((void**)&y,   g_y);
    cudaGetSymbolAddress((void**)&act, g_act);

    cudaFuncSetAttribute(flash_attn_kernel,
                         cudaFuncAttributeMaxDynamicSharedMemorySize, FLASH_SMEM);

    embed_kernel<<<(MROWS * EMB / 4 + 255) / 256, 256>>>(idx, wte, wpe, x);

    for (int l = 0; l < NL; l++) {
        layernorm_kernel<<<MROWS, 192>>>(x, ln1_g + l * EMB, ln1_b + l * EMB, h);

        gemm_tc<false, false, true><<<dim3(3 * EMB / 128, MROWS / TCBM), 256>>>(
            h, attn_w + (size_t)l * EMB * 3 * EMB, attn_b + l * 3 * EMB, qkv,
            MROWS, 3 * EMB, EMB);

        flash_attn_kernel<<<dim3(SEQ / BQ, NH, BATCH), 256, FLASH_SMEM>>>(qkv, y);

        gemm_tc<false, true, true><<<dim3(EMB / 128, MROWS / TCBM), 256>>>(
            y, proj_w + (size_t)l * EMB * EMB, proj_b + l * EMB, x,
            MROWS, EMB, EMB);

        layernorm_kernel<<<MROWS, 192>>>(x, ln2_g + l * EMB, ln2_b + l * EMB, h);

        gemm_tc<true, false, true><<<dim3(4 * EMB / 128, MROWS / TCBM), 256>>>(
            h, mlp_w1 + (size_t)l * EMB * 4 * EMB, mlp_b1 + l * 4 * EMB, act,
            MROWS, 4 * EMB, EMB);

        gemm_tc<false, true, true><<<dim3(EMB / 128, MROWS / TCBM), 256>>>(
            act, mlp_w2 + (size_t)l * 4 * EMB * EMB, mlp_b2 + l * EMB, x,
            MROWS, EMB, 4 * EMB);
    }

    layernorm_kernel<<<MROWS, 192>>>(x, lnf_g, lnf_b, h);

    gemm_tc<false, false, false><<<dim3((VOCAB + 127) / 128, MROWS / TCBM), 256>>>(
        h, head_w, nullptr, out, MROWS, VOCAB, EMB);
}